// round 2
// baseline (speedup 1.0000x reference)
#include <cuda_runtime.h>
#include <cstdint>

#define MTOK  2048
#define DDIM  1024
#define IDIM  2048
#define ENUM  8
#define NPAIR 4096   // MTOK * TOPK

// ---------------- scratch (no allocations allowed) ----------------
__device__ int   g_count[ENUM];
__device__ int   g_off[ENUM];
__device__ int   g_rowlist[NPAIR];                  // pair indices grouped by expert
__device__ float g_act[(size_t)NPAIR * IDIM];       // 32 MB gate activations

// ---------------- helpers ----------------
__device__ __forceinline__ float to_tf32(float x) {
    // round-to-nearest tf32 (unbiased). Truncation (raw bits) would bias the
    // whole dot product by ~-1e-3 relative and fail the 1e-3 threshold.
    uint32_t u;
    asm("cvt.rna.tf32.f32 %0, %1;" : "=r"(u) : "f"(x));
    return __uint_as_float(u);
}

__device__ __forceinline__ void mma8(float* c, const uint32_t* a, const uint32_t* b) {
    asm volatile(
        "mma.sync.aligned.m16n8k8.row.col.f32.tf32.tf32.f32 "
        "{%0,%1,%2,%3}, {%4,%5,%6,%7}, {%8,%9}, {%0,%1,%2,%3};\n"
        : "+f"(c[0]), "+f"(c[1]), "+f"(c[2]), "+f"(c[3])
        : "r"(a[0]), "r"(a[1]), "r"(a[2]), "r"(a[3]), "r"(b[0]), "r"(b[1]));
}

// ---------------- routing: counts -> offsets -> permutation ----------------
// NOTE: expert_indices is int32 on device (JAX x64 is disabled by default, so
// the requested int64 silently becomes int32). Reading int64 here was the
// round-1 bug (rel_err 1.33 from garbage routing).
__global__ void route_kernel(const int* __restrict__ idx) {
    __shared__ int sc[ENUM];
    __shared__ int scur[ENUM];
    int tid = threadIdx.x;
    if (tid < ENUM) sc[tid] = 0;
    __syncthreads();
    for (int p = tid; p < NPAIR; p += blockDim.x)
        atomicAdd(&sc[idx[p]], 1);
    __syncthreads();
    if (tid == 0) {
        int o = 0;
        for (int e = 0; e < ENUM; e++) {
            g_count[e] = sc[e];
            g_off[e]   = o;
            scur[e]    = o;
            o += sc[e];
        }
    }
    __syncthreads();
    for (int p = tid; p < NPAIR; p += blockDim.x) {
        int e = idx[p];
        int pos = atomicAdd(&scur[e], 1);
        g_rowlist[pos] = p;
    }
}

// ---------------- GEMM1: h = x @ w13_e^T (both halves) + silu-gate ----------------
// CTA tile: 128 rows x 64 gate cols (computes 64 cols of x1 AND matching 64 of x3).
// 8 warps (4m x 2n), warp tile 32x32 per half. BK=16, SMEM stride 20 (conflict-free).
__global__ __launch_bounds__(256) void gemm1_kernel(const float* __restrict__ x,
                                                    const float* __restrict__ w13) {
    int e     = blockIdx.z;
    int cnt   = g_count[e];
    int mbase = blockIdx.y * 128;
    if (mbase >= cnt) return;
    int nbase = blockIdx.x * 64;
    int off   = g_off[e];
    const float* w13e = w13 + (size_t)e * 2 * IDIM * DDIM;

    __shared__ float As[128][20];
    __shared__ float B1s[64][20];
    __shared__ float B3s[64][20];

    int tid  = threadIdx.x;
    int lane = tid & 31, wp = tid >> 5;
    int wr = wp >> 1, wc = wp & 1;          // 4 x 2 warp grid
    int g  = lane >> 2, t = lane & 3;

    // global->reg staging (A: 2 float4/thread, B1/B3: 1 float4/thread)
    int arow0 = tid >> 2, arow1 = 64 + (tid >> 2);
    int kk    = (tid & 3) * 4;
    int m0 = mbase + arow0, m1 = mbase + arow1;
    int tok0 = (m0 < cnt) ? (g_rowlist[off + m0] >> 1) : 0;   // TOPK=2: token = pair>>1
    int tok1 = (m1 < cnt) ? (g_rowlist[off + m1] >> 1) : 0;
    const float* a0base = x + (size_t)tok0 * DDIM + kk;
    const float* a1base = x + (size_t)tok1 * DDIM + kk;
    int brow = tid >> 2;
    const float* b1base = w13e + (size_t)(nbase + brow) * DDIM + kk;
    const float* b3base = w13e + (size_t)(IDIM + nbase + brow) * DDIM + kk;

    float c[2][2][4][4];                     // [half][mt][nt][frag]
#pragma unroll
    for (int h = 0; h < 2; h++)
#pragma unroll
        for (int mt = 0; mt < 2; mt++)
#pragma unroll
            for (int nt = 0; nt < 4; nt++)
#pragma unroll
                for (int i = 0; i < 4; i++) c[h][mt][nt][i] = 0.f;

    float4 pa0 = *(const float4*)(a0base);
    float4 pa1 = *(const float4*)(a1base);
    float4 pb1 = *(const float4*)(b1base);
    float4 pb3 = *(const float4*)(b3base);

    for (int k0 = 0; k0 < DDIM; k0 += 16) {
        As[arow0][kk + 0] = to_tf32(pa0.x); As[arow0][kk + 1] = to_tf32(pa0.y);
        As[arow0][kk + 2] = to_tf32(pa0.z); As[arow0][kk + 3] = to_tf32(pa0.w);
        As[arow1][kk + 0] = to_tf32(pa1.x); As[arow1][kk + 1] = to_tf32(pa1.y);
        As[arow1][kk + 2] = to_tf32(pa1.z); As[arow1][kk + 3] = to_tf32(pa1.w);
        B1s[brow][kk + 0] = to_tf32(pb1.x); B1s[brow][kk + 1] = to_tf32(pb1.y);
        B1s[brow][kk + 2] = to_tf32(pb1.z); B1s[brow][kk + 3] = to_tf32(pb1.w);
        B3s[brow][kk + 0] = to_tf32(pb3.x); B3s[brow][kk + 1] = to_tf32(pb3.y);
        B3s[brow][kk + 2] = to_tf32(pb3.z); B3s[brow][kk + 3] = to_tf32(pb3.w);
        __syncthreads();
        if (k0 + 16 < DDIM) {                // prefetch next tile under compute
            pa0 = *(const float4*)(a0base + k0 + 16);
            pa1 = *(const float4*)(a1base + k0 + 16);
            pb1 = *(const float4*)(b1base + k0 + 16);
            pb3 = *(const float4*)(b3base + k0 + 16);
        }
#pragma unroll
        for (int ks = 0; ks < 16; ks += 8) {
            uint32_t af[2][4];
#pragma unroll
            for (int mt = 0; mt < 2; mt++) {
                int r = wr * 32 + mt * 16 + g;
                af[mt][0] = __float_as_uint(As[r][ks + t]);
                af[mt][1] = __float_as_uint(As[r + 8][ks + t]);
                af[mt][2] = __float_as_uint(As[r][ks + t + 4]);
                af[mt][3] = __float_as_uint(As[r + 8][ks + t + 4]);
            }
#pragma unroll
            for (int nt = 0; nt < 4; nt++) {
                int n = wc * 32 + nt * 8 + g;
                uint32_t b1f[2] = { __float_as_uint(B1s[n][ks + t]),
                                    __float_as_uint(B1s[n][ks + t + 4]) };
                uint32_t b3f[2] = { __float_as_uint(B3s[n][ks + t]),
                                    __float_as_uint(B3s[n][ks + t + 4]) };
#pragma unroll
                for (int mt = 0; mt < 2; mt++) {
                    mma8(c[0][mt][nt], af[mt], b1f);
                    mma8(c[1][mt][nt], af[mt], b3f);
                }
            }
        }
        __syncthreads();
    }

    // fused silu(x1)*x3 epilogue -> g_act (rows stay in permuted/grouped order)
    int rowbase = off + mbase;
#pragma unroll
    for (int mt = 0; mt < 2; mt++) {
        int r0 = wr * 32 + mt * 16 + g;
#pragma unroll
        for (int nt = 0; nt < 4; nt++) {
            int col = nbase + wc * 32 + nt * 8 + 2 * t;
            if (mbase + r0 < cnt) {
                float v1a = c[0][mt][nt][0], v3a = c[1][mt][nt][0];
                float v1b = c[0][mt][nt][1], v3b = c[1][mt][nt][1];
                float ga = v1a / (1.f + expf(-v1a)) * v3a;
                float gb = v1b / (1.f + expf(-v1b)) * v3b;
                *(float2*)&g_act[(size_t)(rowbase + r0) * IDIM + col] = make_float2(ga, gb);
            }
            if (mbase + r0 + 8 < cnt) {
                float v1a = c[0][mt][nt][2], v3a = c[1][mt][nt][2];
                float v1b = c[0][mt][nt][3], v3b = c[1][mt][nt][3];
                float ga = v1a / (1.f + expf(-v1a)) * v3a;
                float gb = v1b / (1.f + expf(-v1b)) * v3b;
                *(float2*)&g_act[(size_t)(rowbase + r0 + 8) * IDIM + col] = make_float2(ga, gb);
            }
        }
    }
}

// ---------------- GEMM2: out = g_act @ w2_e^T, scatter to d_out ----------------
// CTA tile: 128 rows x 128 out cols, BK=16. 8 warps (4m x 2n), warp tile 32x64.
__global__ __launch_bounds__(256) void gemm2_kernel(const float* __restrict__ w2,
                                                    float* __restrict__ out) {
    int e     = blockIdx.z;
    int cnt   = g_count[e];
    int mbase = blockIdx.y * 128;
    if (mbase >= cnt) return;
    int cbase = blockIdx.x * 128;
    int off   = g_off[e];
    const float* w2e = w2 + (size_t)e * DDIM * IDIM;

    __shared__ float As[128][20];
    __shared__ float Bs[128][20];

    int tid  = threadIdx.x;
    int lane = tid & 31, wp = tid >> 5;
    int wr = wp >> 1, wc = wp & 1;
    int g  = lane >> 2, t = lane & 3;

    int r0 = tid >> 2, r1 = 64 + (tid >> 2);
    int kk = (tid & 3) * 4;
    // clamp gather index into scratch (padding rows compute garbage but are never stored)
    int ga0 = off + mbase + r0; if (ga0 > NPAIR - 1) ga0 = NPAIR - 1;
    int ga1 = off + mbase + r1; if (ga1 > NPAIR - 1) ga1 = NPAIR - 1;
    const float* a0base = g_act + (size_t)ga0 * IDIM + kk;
    const float* a1base = g_act + (size_t)ga1 * IDIM + kk;
    const float* b0base = w2e + (size_t)(cbase + r0) * IDIM + kk;
    const float* b1base = w2e + (size_t)(cbase + r1) * IDIM + kk;

    float c[2][8][4];
#pragma unroll
    for (int mt = 0; mt < 2; mt++)
#pragma unroll
        for (int nt = 0; nt < 8; nt++)
#pragma unroll
            for (int i = 0; i < 4; i++) c[mt][nt][i] = 0.f;

    float4 pa0 = *(const float4*)(a0base);
    float4 pa1 = *(const float4*)(a1base);
    float4 pb0 = *(const float4*)(b0base);
    float4 pb1 = *(const float4*)(b1base);

    for (int k0 = 0; k0 < IDIM; k0 += 16) {
        As[r0][kk + 0] = to_tf32(pa0.x); As[r0][kk + 1] = to_tf32(pa0.y);
        As[r0][kk + 2] = to_tf32(pa0.z); As[r0][kk + 3] = to_tf32(pa0.w);
        As[r1][kk + 0] = to_tf32(pa1.x); As[r1][kk + 1] = to_tf32(pa1.y);
        As[r1][kk + 2] = to_tf32(pa1.z); As[r1][kk + 3] = to_tf32(pa1.w);
        Bs[r0][kk + 0] = to_tf32(pb0.x); Bs[r0][kk + 1] = to_tf32(pb0.y);
        Bs[r0][kk + 2] = to_tf32(pb0.z); Bs[r0][kk + 3] = to_tf32(pb0.w);
        Bs[r1][kk + 0] = to_tf32(pb1.x); Bs[r1][kk + 1] = to_tf32(pb1.y);
        Bs[r1][kk + 2] = to_tf32(pb1.z); Bs[r1][kk + 3] = to_tf32(pb1.w);
        __syncthreads();
        if (k0 + 16 < IDIM) {
            pa0 = *(const float4*)(a0base + k0 + 16);
            pa1 = *(const float4*)(a1base + k0 + 16);
            pb0 = *(const float4*)(b0base + k0 + 16);
            pb1 = *(const float4*)(b1base + k0 + 16);
        }
#pragma unroll
        for (int ks = 0; ks < 16; ks += 8) {
            uint32_t af[2][4];
#pragma unroll
            for (int mt = 0; mt < 2; mt++) {
                int r = wr * 32 + mt * 16 + g;
                af[mt][0] = __float_as_uint(As[r][ks + t]);
                af[mt][1] = __float_as_uint(As[r + 8][ks + t]);
                af[mt][2] = __float_as_uint(As[r][ks + t + 4]);
                af[mt][3] = __float_as_uint(As[r + 8][ks + t + 4]);
            }
#pragma unroll
            for (int nt = 0; nt < 8; nt++) {
                int n = wc * 64 + nt * 8 + g;
                uint32_t bf[2] = { __float_as_uint(Bs[n][ks + t]),
                                   __float_as_uint(Bs[n][ks + t + 4]) };
#pragma unroll
                for (int mt = 0; mt < 2; mt++) mma8(c[mt][nt], af[mt], bf);
            }
        }
        __syncthreads();
    }

    // scatter epilogue: out[pair][col]
#pragma unroll
    for (int mt = 0; mt < 2; mt++) {
        int r = wr * 32 + mt * 16 + g;
#pragma unroll
        for (int nt = 0; nt < 8; nt++) {
            int col = cbase + wc * 64 + nt * 8 + 2 * t;
            if (mbase + r < cnt) {
                int pair = g_rowlist[off + mbase + r];
                *(float2*)&out[(size_t)pair * DDIM + col] =
                    make_float2(c[mt][nt][0], c[mt][nt][1]);
            }
            if (mbase + r + 8 < cnt) {
                int pair = g_rowlist[off + mbase + r + 8];
                *(float2*)&out[(size_t)pair * DDIM + col] =
                    make_float2(c[mt][nt][2], c[mt][nt][3]);
            }
        }
    }
}

// ---------------- launch ----------------
extern "C" void kernel_launch(void* const* d_in, const int* in_sizes, int n_in,
                              void* d_out, int out_size) {
    (void)in_sizes; (void)n_in; (void)out_size;
    const float* x   = (const float*)d_in[0];
    const float* w13 = (const float*)d_in[1];
    const float* w2  = (const float*)d_in[2];
    const int*   idx = (const int*)d_in[3];
    float* out = (float*)d_out;

    route_kernel<<<1, 256>>>(idx);
    // oversized grids; CTAs early-exit past each expert's row count
    gemm1_kernel<<<dim3(IDIM / 64, NPAIR / 128, ENUM), 256>>>(x, w13);
    gemm2_kernel<<<dim3(DDIM / 128, NPAIR / 128, ENUM), 256>>>(w2, out);
}